// round 1
// baseline (speedup 1.0000x reference)
#include <cuda_runtime.h>
#include <math.h>

// Problem constants
#define NCHUNK 32
#define NBATCH 64
#define HALF   128
#define SIZE   (2 * HALF)            // 256
#define NROWS  (NCHUNK * NBATCH)     // 2048
#define C_SCALE 1e-4f
#define M_SCALE 1e-5f

// ydot occupies the first NROWS*SIZE floats of d_out; J follows.
#define YDOT_FLOATS (NROWS * SIZE)           // 524288
#define JB_FLOATS   (SIZE * SIZE)            // 65536 (256 KB)

// Scratch: the 256x256 constant Jacobian block
__device__ float g_Jb[JB_FLOATS];

// ---------------------------------------------------------------------------
// Kernel 1: build Jb (256 blocks x 256 threads; r = blockIdx, c = threadIdx)
// ---------------------------------------------------------------------------
__global__ void jb_kernel(const float* __restrict__ K,
                          const float* __restrict__ C,
                          const float* __restrict__ M) {
    int r = blockIdx.x;
    int c = threadIdx.x;
    float val = 0.0f;
    if (r < HALF) {
        // top-right identity block
        val = (c == r + HALF) ? 1.0f : 0.0f;
    } else {
        int i = r - HALF;
        float Mi = M[i] * M_SCALE;
        if (c < HALF) {
            // ku tridiagonal
            int j = c;
            if (j == i) {
                val = -K[i] / Mi;
                if (i > 0) val -= K[i - 1] / Mi;
            } else if (j == i + 1) {
                val = K[i] / Mi;          // i <= 126 guaranteed (j <= 127)
            } else if (j == i - 1) {
                val = K[i - 1] / Mi;
            }
        } else {
            // kv tridiagonal (damping, scaled)
            int j = c - HALF;
            if (j == i) {
                val = -(C[i] * C_SCALE) / Mi;
                if (i > 0) val -= (C[i - 1] * C_SCALE) / Mi;
            } else if (j == i + 1) {
                val = (C[i] * C_SCALE) / Mi;
            } else if (j == i - 1) {
                val = (C[i - 1] * C_SCALE) / Mi;
            }
        }
    }
    g_Jb[r * SIZE + c] = val;
}

// ---------------------------------------------------------------------------
// Kernel 2: ydot (2048 blocks x 256 threads; one block per (chunk,batch) row)
// ---------------------------------------------------------------------------
__global__ void ydot_kernel(const float* __restrict__ t,
                            const float* __restrict__ y,
                            const float* __restrict__ K,
                            const float* __restrict__ C,
                            const float* __restrict__ M,
                            float* __restrict__ out) {
    __shared__ float sm[SIZE];   // [u(128) | v(128)]
    int row = blockIdx.x;
    int tid = threadIdx.x;
    sm[tid] = y[row * SIZE + tid];
    __syncthreads();

    float res;
    if (tid < HALF) {
        // ydot[:half] = v
        res = sm[HALF + tid];
    } else {
        int i = tid - HALF;
        float Mi = M[i] * M_SCALE;
        float acc = 0.0f;
        if (i < HALF - 1) {
            float f = K[i] * (sm[i + 1] - sm[i])
                    + (C[i] * C_SCALE) * (sm[HALF + i + 1] - sm[HALF + i]);
            acc += f / Mi;
        }
        if (i > 0) {
            float fm = K[i - 1] * (sm[i] - sm[i - 1])
                     + (C[i - 1] * C_SCALE) * (sm[HALF + i] - sm[HALF + i - 1]);
            acc -= fm / Mi;
        }
        if (i == HALF - 1) {
            acc -= (K[HALF - 1] * sm[HALF - 1]
                  + (C[HALF - 1] * C_SCALE) * sm[SIZE - 1]) / Mi;
        }
        if (i == 0) {
            acc += sinf(t[row]) / Mi;
        }
        res = acc;
    }
    out[row * SIZE + tid] = res;
}

// ---------------------------------------------------------------------------
// Kernel 3: broadcast J. Grid = 16 segments x 128 block-groups = 2048 blocks.
// Each block: 256 threads, each thread holds 4 float4 of its 16KB Jb segment
// in REGISTERS, then stores them to 16 consecutive batch copies.
// Stores are fully coalesced 128-bit (warp -> 512B contiguous).
// ---------------------------------------------------------------------------
#define SEGS 16            // 16 segments of 1024 float4 (16 KB) each
#define GRP  128           // block-groups per segment
#define CPB  (NROWS / GRP) // 16 copies per block

__global__ void bcast_kernel(float* __restrict__ out) {
    const float4* __restrict__ jb4 = reinterpret_cast<const float4*>(g_Jb);
    float4* __restrict__ j4 = reinterpret_cast<float4*>(out + YDOT_FLOATS);

    int s = blockIdx.x & (SEGS - 1);       // segment 0..15
    int g = blockIdx.x >> 4;               // group   0..127
    int tid = threadIdx.x;

    int segBase = s * 1024;                // float4 index within one Jb copy

    // Load this thread's 4 float4 once (L2-resident Jb)
    float4 r0 = jb4[segBase + 0 * 256 + tid];
    float4 r1 = jb4[segBase + 1 * 256 + tid];
    float4 r2 = jb4[segBase + 2 * 256 + tid];
    float4 r3 = jb4[segBase + 3 * 256 + tid];

    int c0 = g * CPB;
    #pragma unroll 4
    for (int k = 0; k < CPB; k++) {
        // each Jb copy = 16384 float4
        float4* dst = j4 + (long long)(c0 + k) * 16384 + segBase + tid;
        dst[0 * 256] = r0;
        dst[1 * 256] = r1;
        dst[2 * 256] = r2;
        dst[3 * 256] = r3;
    }
}

// ---------------------------------------------------------------------------
extern "C" void kernel_launch(void* const* d_in, const int* in_sizes, int n_in,
                              void* d_out, int out_size) {
    const float* t = (const float*)d_in[0];
    const float* y = (const float*)d_in[1];
    const float* K = (const float*)d_in[2];
    const float* C = (const float*)d_in[3];
    const float* M = (const float*)d_in[4];
    float* out = (float*)d_out;

    jb_kernel<<<SIZE, SIZE>>>(K, C, M);
    ydot_kernel<<<NROWS, SIZE>>>(t, y, K, C, M, out);
    bcast_kernel<<<SEGS * GRP, SIZE>>>(out);
}

// round 2
// speedup vs baseline: 1.0612x; 1.0612x over previous
#include <cuda_runtime.h>
#include <math.h>

// Problem constants
#define NCHUNK 32
#define NBATCH 64
#define HALF   128
#define SIZE   (2 * HALF)            // 256
#define NROWS  (NCHUNK * NBATCH)     // 2048
#define C_SCALE 1e-4f
#define M_SCALE 1e-5f

// ydot occupies the first NROWS*SIZE floats of d_out; J follows.
#define YDOT_FLOATS (NROWS * SIZE)   // 524288

// Grid mapping for the J broadcast:
//   2048 blocks = 16 segments x 128 groups. Each block owns a 16 KB segment
//   of the 256 KB Jb block (held in registers) and writes it to 16 batch copies.
#define SEGS 16
#define GRP  128
#define CPB  (NROWS / GRP)           // 16 copies per block

// ---------------------------------------------------------------------------
// Closed-form Jb[r][c] (256x256):
//   top-left 128x128:    0
//   top-right 128x128:   identity
//   bottom-left (ku):    tridiagonal stiffness
//   bottom-right (kv):   tridiagonal damping (C_SCALE)
// ---------------------------------------------------------------------------
__device__ __forceinline__ float jb_val(int r, int c,
                                        const float* __restrict__ K,
                                        const float* __restrict__ C,
                                        const float* __restrict__ M) {
    if (r < HALF) {
        return (c == r + HALF) ? 1.0f : 0.0f;
    }
    int i = r - HALF;
    int j = (c < HALF) ? c : (c - HALF);
    // band check first: |j - i| <= 1, else zero (vast majority)
    int d = j - i;
    if (d < -1 || d > 1) return 0.0f;

    float Mi = M[i] * M_SCALE;
    if (c < HALF) {
        if (d == 0) {
            float v = -K[i] / Mi;
            if (i > 0) v -= K[i - 1] / Mi;
            return v;
        } else if (d == 1) {
            return K[i] / Mi;            // i <= 126 guaranteed
        } else {                          // d == -1
            return K[i - 1] / Mi;
        }
    } else {
        if (d == 0) {
            float v = -(C[i] * C_SCALE) / Mi;
            if (i > 0) v -= (C[i - 1] * C_SCALE) / Mi;
            return v;
        } else if (d == 1) {
            return (C[i] * C_SCALE) / Mi;
        } else {
            return (C[i - 1] * C_SCALE) / Mi;
        }
    }
}

// ---------------------------------------------------------------------------
// ONE fused kernel: 2048 blocks x 256 threads.
//   Block b: computes ydot row b (prologue), then broadcasts its register-
//   resident 16 KB Jb segment to 16 batch copies with coalesced 128-bit stores.
// ---------------------------------------------------------------------------
__global__ void __launch_bounds__(SIZE, 4)
fused_kernel(const float* __restrict__ t,
             const float* __restrict__ y,
             const float* __restrict__ K,
             const float* __restrict__ C,
             const float* __restrict__ M,
             float* __restrict__ out) {
    __shared__ float sm[SIZE];   // [u(128) | v(128)]
    int b   = blockIdx.x;
    int tid = threadIdx.x;

    // ---- Part A: ydot for row b -------------------------------------------
    sm[tid] = y[b * SIZE + tid];

    // ---- Part B prologue: compute this thread's 16 Jb values (registers) --
    // float4 index within one Jb copy: segBase + q*256 + tid, q = 0..3
    int s = b & (SEGS - 1);
    int g = b >> 4;
    int segBase = s * 1024;                    // in float4 units

    float4 jr[4];
    #pragma unroll
    for (int q = 0; q < 4; q++) {
        int e = (segBase + q * 256 + tid) * 4; // linear float index in Jb
        int r = e >> 8;
        int c = e & (SIZE - 1);
        jr[q].x = jb_val(r, c + 0, K, C, M);
        jr[q].y = jb_val(r, c + 1, K, C, M);
        jr[q].z = jb_val(r, c + 2, K, C, M);
        jr[q].w = jb_val(r, c + 3, K, C, M);
    }

    __syncthreads();

    // ---- Part A compute + store -------------------------------------------
    float res;
    if (tid < HALF) {
        res = sm[HALF + tid];                  // ydot[:half] = v
    } else {
        int i = tid - HALF;
        float Mi = M[i] * M_SCALE;
        float acc = 0.0f;
        if (i < HALF - 1) {
            float f = K[i] * (sm[i + 1] - sm[i])
                    + (C[i] * C_SCALE) * (sm[HALF + i + 1] - sm[HALF + i]);
            acc += f / Mi;
        }
        if (i > 0) {
            float fm = K[i - 1] * (sm[i] - sm[i - 1])
                     + (C[i - 1] * C_SCALE) * (sm[HALF + i] - sm[HALF + i - 1]);
            acc -= fm / Mi;
        }
        if (i == HALF - 1) {
            acc -= (K[HALF - 1] * sm[HALF - 1]
                  + (C[HALF - 1] * C_SCALE) * sm[SIZE - 1]) / Mi;
        }
        if (i == 0) {
            acc += sinf(t[b]) / Mi;
        }
        res = acc;
    }
    out[b * SIZE + tid] = res;

    // ---- Part B: broadcast J (register replay, coalesced STG.128) ---------
    float4* __restrict__ j4 = reinterpret_cast<float4*>(out + YDOT_FLOATS);
    int c0 = g * CPB;
    #pragma unroll 4
    for (int k = 0; k < CPB; k++) {
        float4* dst = j4 + (long long)(c0 + k) * 16384 + segBase + tid;
        dst[0 * 256] = jr[0];
        dst[1 * 256] = jr[1];
        dst[2 * 256] = jr[2];
        dst[3 * 256] = jr[3];
    }
}

// ---------------------------------------------------------------------------
extern "C" void kernel_launch(void* const* d_in, const int* in_sizes, int n_in,
                              void* d_out, int out_size) {
    const float* t = (const float*)d_in[0];
    const float* y = (const float*)d_in[1];
    const float* K = (const float*)d_in[2];
    const float* C = (const float*)d_in[3];
    const float* M = (const float*)d_in[4];
    float* out = (float*)d_out;

    fused_kernel<<<NROWS, SIZE>>>(t, y, K, C, M, out);
}